// round 9
// baseline (speedup 1.0000x reference)
#include <cuda_runtime.h>
#include <cuda_bf16.h>
#include <cstdint>

// TSM: x (B=4, T=16, H=64, W=64, C=256) fp32
// out[..., 0:64)    = x[t+1, ..., 0:64)   (0 at t=T-1)
// out[..., 64:128)  = x[t-1, ..., 64:128) (0 at t=0)
// out[..., 128:256) = x[t, ..., 128:256)
//
// FINAL — converged configuration (best measured: 73.54-73.76us kernel /
// 80.35us bench, DRAM 81%, 6.42 TB/s).
//
// Convergence evidence (R1-R8): seven structurally distinct variants
// (128/256-bit accesses, unroll 4/8, per-thread vs block-strided, warp-uniform
// dt, persistent grid, .cs / L2::256B hints) all plateau at 6.33-6.44 TB/s ==
// the B300 LTS chip-throughput cap (~6300 B/cyc, path-independent — LDG ≡ TMA,
// so a TMA pipeline cannot exceed it either). SM pipes are <9% utilized;
// occupancy sweeps 60-89% had no effect. Traffic is minimal: each output byte
// written once (harness requires full write), each needed input byte read
// once, boundary reads skipped, no reuse exists in the dataflow.
//
// float4 units: c4 = i & 63; t = (i >> 18) & 15; slab stride = 1<<18 float4.
// dt = +1 (c4<16), -1 (c4<32), 0 otherwise. Invalid src -> 0.
// Block-strided unroll x8: every LDG.128/STG.128 perfectly coalesced
// (consecutive lanes -> consecutive float4), 8 independent loads in flight
// per thread before the store batch; .cs hints keep the 512MiB single-touch
// stream from thrashing L2.

static constexpr int BTSTRIDE = 1 << 18;      // float4 per (b,t) slab
static constexpr long long N4 = 16777216LL;   // total float4
static constexpr int UNROLL = 8;
static constexpr int TPB = 256;
static constexpr int F4_PER_BLOCK = TPB * UNROLL; // 2048

__global__ __launch_bounds__(TPB) void tsm_kernel(const float4* __restrict__ in,
                                                  float4* __restrict__ out)
{
    long long blockBase = (long long)(blockIdx.x) * F4_PER_BLOCK;
    int tid = threadIdx.x;

    float4 v[UNROLL];

    #pragma unroll
    for (int u = 0; u < UNROLL; ++u) {
        long long i = blockBase + u * TPB + tid;
        int c4 = (int)(i & 63);
        int t  = (int)((i >> 18) & 15);

        int dt = (c4 < 16) ? 1 : ((c4 < 32) ? -1 : 0);
        int ts = t + dt;
        bool valid = (unsigned)ts < 16u;

        v[u] = make_float4(0.f, 0.f, 0.f, 0.f);
        if (valid) {
            v[u] = __ldcs(&in[i + (long long)dt * BTSTRIDE]);
        }
    }

    #pragma unroll
    for (int u = 0; u < UNROLL; ++u) {
        long long i = blockBase + u * TPB + tid;
        __stcs(&out[i], v[u]);
    }
}

extern "C" void kernel_launch(void* const* d_in, const int* in_sizes, int n_in,
                              void* d_out, int out_size)
{
    const float4* in = (const float4*)d_in[0];
    float4* out = (float4*)d_out;

    int blocks = (int)(N4 / F4_PER_BLOCK); // 8192
    tsm_kernel<<<blocks, TPB>>>(in, out);
}

// round 10
// speedup vs baseline: 1.0036x; 1.0036x over previous
#include <cuda_runtime.h>
#include <cuda_bf16.h>
#include <cstdint>

// TSM: x (B=4, T=16, H=64, W=64, C=256) fp32
// out[..., 0:64)    = x[t+1, ..., 0:64)   (0 at t=T-1)
// out[..., 64:128)  = x[t-1, ..., 64:128) (0 at t=0)
// out[..., 128:256) = x[t, ..., 128:256)
//
// FINAL — converged configuration (best measured: 73.12us kernel /
// 80.35us bench, DRAM 81.7%, 6.47 TB/s).
//
// Convergence evidence (R1-R9): seven structurally distinct variants
// (128/256-bit accesses, unroll 4/8, per-thread vs block-strided, warp-uniform
// dt, persistent grid, .cs / L2::256B hints) all plateau at 6.33-6.47 TB/s ==
// the B300 LTS chip-throughput cap (~6300 B/cyc, path-independent — LDG ≡ TMA,
// so a TMA pipeline cannot exceed it either). SM pipes are <9% utilized;
// occupancy sweeps 60-89% had no effect. Traffic is minimal: each output byte
// written once (harness requires full write), each needed input byte read
// once, boundary reads skipped, no reuse exists in the dataflow. Three
// consecutive reproductions (R8, R9) confirm stability.
//
// float4 units: c4 = i & 63; t = (i >> 18) & 15; slab stride = 1<<18 float4.
// dt = +1 (c4<16), -1 (c4<32), 0 otherwise. Invalid src -> 0.
// Block-strided unroll x8: every LDG.128/STG.128 perfectly coalesced
// (consecutive lanes -> consecutive float4), 8 independent loads in flight
// per thread before the store batch; .cs hints keep the 512MiB single-touch
// stream from thrashing L2.

static constexpr int BTSTRIDE = 1 << 18;      // float4 per (b,t) slab
static constexpr long long N4 = 16777216LL;   // total float4
static constexpr int UNROLL = 8;
static constexpr int TPB = 256;
static constexpr int F4_PER_BLOCK = TPB * UNROLL; // 2048

__global__ __launch_bounds__(TPB) void tsm_kernel(const float4* __restrict__ in,
                                                  float4* __restrict__ out)
{
    long long blockBase = (long long)(blockIdx.x) * F4_PER_BLOCK;
    int tid = threadIdx.x;

    float4 v[UNROLL];

    #pragma unroll
    for (int u = 0; u < UNROLL; ++u) {
        long long i = blockBase + u * TPB + tid;
        int c4 = (int)(i & 63);
        int t  = (int)((i >> 18) & 15);

        int dt = (c4 < 16) ? 1 : ((c4 < 32) ? -1 : 0);
        int ts = t + dt;
        bool valid = (unsigned)ts < 16u;

        v[u] = make_float4(0.f, 0.f, 0.f, 0.f);
        if (valid) {
            v[u] = __ldcs(&in[i + (long long)dt * BTSTRIDE]);
        }
    }

    #pragma unroll
    for (int u = 0; u < UNROLL; ++u) {
        long long i = blockBase + u * TPB + tid;
        __stcs(&out[i], v[u]);
    }
}

extern "C" void kernel_launch(void* const* d_in, const int* in_sizes, int n_in,
                              void* d_out, int out_size)
{
    const float4* in = (const float4*)d_in[0];
    float4* out = (float4*)d_out;

    int blocks = (int)(N4 / F4_PER_BLOCK); // 8192
    tsm_kernel<<<blocks, TPB>>>(in, out);
}